// round 15
// baseline (speedup 1.0000x reference)
#include <cuda_runtime.h>

#define DEG 32
#define D 128
#define NEG_SLOPE 0.01f

// Streaming loads: evict-first policy + 256B L2 prefetch hint.
__device__ __forceinline__ float4 ldcs_pf256(const float4* p) {
    float4 v;
    asm("ld.global.cs.L2::256B.v4.f32 {%0,%1,%2,%3}, [%4];"
        : "=f"(v.x), "=f"(v.y), "=f"(v.z), "=f"(v.w)
        : "l"(p));
    return v;
}
__device__ __forceinline__ float ldcs_pf256_f(const float* p) {
    float v;
    asm("ld.global.cs.L2::256B.f32 %0, [%1];" : "=f"(v) : "l"(p));
    return v;
}

// 2 nodes per CTA: each 128-thread half runs the champion code path on its
// own node. Halves CTA count (less dispatch overhead), same dense mapping,
// identical per-warp memory pattern, same warps/SM.
__global__ __launch_bounds__(256, 4)
void gat_reduce_kernel(const float* __restrict__ a1,
                       const float* __restrict__ a2,
                       const float* __restrict__ ft,
                       float* __restrict__ out,
                       int N)
{
    const int half = threadIdx.x >> 7;           // 0 or 1: which node
    const int tid  = threadIdx.x & 127;          // 0..127 within half
    const int warp = tid >> 5;                   // 0..3
    const int lane = tid & 31;
    const int n    = blockIdx.x * 2 + half;

    __shared__ float  s_g[2][DEG];
    __shared__ float  s_a1[2][4];
    __shared__ float  s_e[2][DEG];
    __shared__ float4 s_red[2][4][32];

    if (n < N) {
        const size_t base = (size_t)n * DEG * D;
        const float4* a2v = reinterpret_cast<const float4*>(a2 + base);

        // ---- a1 row sum ----
        float v = ldcs_pf256_f(a1 + (size_t)n * D + tid);
        #pragma unroll
        for (int o = 16; o; o >>= 1) v += __shfl_down_sync(0xFFFFFFFFu, v, o);
        if (lane == 0) s_a1[half][warp] = v;

        // ---- per-neighbor sums: warp w handles g = w*8 .. w*8+7 ----
        float4 x[8];
        #pragma unroll
        for (int i = 0; i < 8; i++) {
            int g = warp * 8 + i;
            x[i] = ldcs_pf256(&a2v[g * (D / 4) + lane]);
        }
        #pragma unroll
        for (int i = 0; i < 8; i++) {
            float s = (x[i].x + x[i].y) + (x[i].z + x[i].w);
            #pragma unroll
            for (int o = 16; o; o >>= 1) s += __shfl_down_sync(0xFFFFFFFFu, s, o);
            if (lane == 0) s_g[half][warp * 8 + i] = s;
        }
    }
    __syncthreads();

    if (n < N) {
        // ---- softmax over 32 neighbors (warp 0 of each half) ----
        if (warp == 0) {
            float s1 = s_a1[half][0] + s_a1[half][1] + s_a1[half][2] + s_a1[half][3];
            float a  = s_g[half][lane] + s1;
            a = (a > 0.0f) ? a : NEG_SLOPE * a;           // leaky relu
            float m = a;
            #pragma unroll
            for (int o = 16; o; o >>= 1) m = fmaxf(m, __shfl_xor_sync(0xFFFFFFFFu, m, o));
            float e = __expf(a - m);
            float sum = e;
            #pragma unroll
            for (int o = 16; o; o >>= 1) sum += __shfl_xor_sync(0xFFFFFFFFu, sum, o);
            s_e[half][lane] = e / sum;
        }
    }
    __syncthreads();

    if (n < N) {
        const size_t base = (size_t)n * DEG * D;
        const float4* ftv = reinterpret_cast<const float4*>(ft + base);

        // ---- weighted accumulation: warp handles g = warp, warp+4, ... ----
        float4 acc = make_float4(0.f, 0.f, 0.f, 0.f);
        #pragma unroll
        for (int i = 0; i < 8; i++) {
            int g = i * 4 + warp;
            float w = s_e[half][g];
            float4 f = ldcs_pf256(&ftv[g * (D / 4) + lane]);
            acc.x += w * f.x;
            acc.y += w * f.y;
            acc.z += w * f.z;
            acc.w += w * f.w;
        }
        s_red[half][warp][lane] = acc;
    }
    __syncthreads();

    if (n < N && warp == 0) {
        float4 r0 = s_red[half][0][lane];
        float4 r1 = s_red[half][1][lane];
        float4 r2 = s_red[half][2][lane];
        float4 r3 = s_red[half][3][lane];
        float4 r;
        r.x = (r0.x + r1.x) + (r2.x + r3.x);
        r.y = (r0.y + r1.y) + (r2.y + r3.y);
        r.z = (r0.z + r1.z) + (r2.z + r3.z);
        r.w = (r0.w + r1.w) + (r2.w + r3.w);
        __stcs(&reinterpret_cast<float4*>(out + (size_t)n * D)[lane], r);
    }
}

extern "C" void kernel_launch(void* const* d_in, const int* in_sizes, int n_in,
                              void* d_out, int out_size)
{
    const float* a1 = (const float*)d_in[0];   // [N, D]
    const float* a2 = (const float*)d_in[1];   // [N, DEG, D]
    const float* ft = (const float*)d_in[2];   // [N, DEG, D]
    float* out = (float*)d_out;                // [N, D]

    int N = in_sizes[0] / D;
    int blocks = (N + 1) / 2;                  // 2 nodes per CTA
    gat_reduce_kernel<<<blocks, 256>>>(a1, a2, ft, out, N);
}